// round 3
// baseline (speedup 1.0000x reference)
#include <cuda_runtime.h>
#include <cuda_bf16.h>
#include <cstdint>

// XingLoss: P=16384 rows, N=1024 float2 points per row.
// segn = 256 segments/row, segment s uses points x[3s..3s+3] (only x[0..768] used).
// term = (cross(v1,v2)>=0) ? relu(-sina) : relu(sina),
// sina = cross(v1,v3)/(|v1||v3|). Output = mean_p( sum_s term / 256 ) * scale.

#define NPTS        1024
#define SEGN        256
#define PTS_USED    769            // points 0..768
#define F4_PER_ROW  385            // ceil(769*2 / 4) float4 staged per row
#define MAX_P       65536

__device__ float g_partials[MAX_P];

__global__ __launch_bounds__(256, 8)
void xing_row_kernel(const float* __restrict__ x, float* __restrict__ partials)
{
    __shared__ float2 sm[F4_PER_ROW * 2];   // 770 float2 = 6160 B
    __shared__ float red[8];

    const int p = blockIdx.x;
    const int t = threadIdx.x;

    // Coalesced staging: 385 float4 per row (row base is 8192B-aligned).
    const float4* __restrict__ row4 =
        reinterpret_cast<const float4*>(x + (size_t)p * (NPTS * 2));
    float4* sm4 = reinterpret_cast<float4*>(sm);
    #pragma unroll
    for (int i = t; i < F4_PER_ROW; i += 256)
        sm4[i] = row4[i];
    __syncthreads();

    // One segment per thread. stride-3 float2 reads: 3s mod 32 is a permutation
    // over a warp -> conflict-free LDS.64.
    const int s = t;
    const float2 p0 = sm[3 * s + 0];
    const float2 p1 = sm[3 * s + 1];
    const float2 p2 = sm[3 * s + 2];
    const float2 p3 = sm[3 * s + 3];

    const float v1x = p1.x - p0.x, v1y = p1.y - p0.y;
    const float v2x = p2.x - p1.x, v2y = p2.y - p1.y;
    const float v3x = p3.x - p2.x, v3y = p3.y - p2.y;

    // sign(s12) == sign(cross12) since |v1||v2| > 0 a.s.
    const float c12 = v1x * v2y - v1y * v2x;
    const float c13 = v1x * v3y - v1y * v3x;
    const float nn  = (v1x * v1x + v1y * v1y) * (v3x * v3x + v3y * v3y);
    const float sina = c13 * rsqrtf(nn);

    float term = (c12 >= 0.0f) ? fmaxf(-sina, 0.0f) : fmaxf(sina, 0.0f);

    // Warp reduce
    #pragma unroll
    for (int off = 16; off > 0; off >>= 1)
        term += __shfl_xor_sync(0xFFFFFFFFu, term, off);
    if ((t & 31) == 0) red[t >> 5] = term;
    __syncthreads();

    if (t < 8) {
        float v = red[t];
        #pragma unroll
        for (int off = 4; off > 0; off >>= 1)
            v += __shfl_xor_sync(0xFFu, v, off);
        if (t == 0) partials[p] = v;   // raw sum of 256 terms for this row
    }
}

__global__ __launch_bounds__(256, 1)
void xing_finalize_kernel(const float* __restrict__ partials, int P,
                          const void* __restrict__ scale_ptr,
                          float* __restrict__ out)
{
    __shared__ double sdata[256];
    const int t = threadIdx.x;

    double acc = 0.0;
    for (int i = t; i < P; i += 256)
        acc += (double)partials[i];
    sdata[t] = acc;
    __syncthreads();

    #pragma unroll
    for (int off = 128; off > 0; off >>= 1) {
        if (t < off) sdata[t] += sdata[t + off];
        __syncthreads();
    }

    if (t == 0) {
        // scale may be int32 or float32 (1 element). Bit-pattern heuristic:
        // a plausible normal float -> float; otherwise interpret as int.
        const int ibits = *reinterpret_cast<const int*>(scale_ptr);
        const float fval = __int_as_float(ibits);
        const float af = fabsf(fval);
        float scale;
        if (af >= 1e-30f && af <= 1e30f) scale = fval;
        else                             scale = (float)ibits;

        const double denom = (double)SEGN * (double)P;
        out[0] = (float)(sdata[0] * (double)scale / denom);
    }
}

extern "C" void kernel_launch(void* const* d_in, const int* in_sizes, int n_in,
                              void* d_out, int out_size)
{
    const float* x = (const float*)d_in[0];
    const void* scale = (n_in > 1) ? d_in[1] : nullptr;

    const int P = in_sizes[0] / (NPTS * 2);   // 16384 for this problem

    float* partials;
    cudaGetSymbolAddress((void**)&partials, g_partials);

    xing_row_kernel<<<P, 256>>>(x, partials);
    xing_finalize_kernel<<<1, 256>>>(partials, P, scale, (float*)d_out);
}

// round 5
// speedup vs baseline: 1.3856x; 1.3856x over previous
#include <cuda_runtime.h>
#include <cuda_bf16.h>
#include <cstdint>

// XingLoss: P=16384 rows, N=1024 float2 points/row. segn=256 segments/row,
// segment s uses points x[3s..3s+3] (only x[0..768] used, 6160 B of 8192 B/row).
// term = (cross(v1,v2)>=0) ? relu(-sina) : relu(sina),
// sina = cross(v1,v3)/(|v1||v3|). out = mean_p( sum_s term / 256 ) * scale.
//
// Single fused kernel: per-row block sum -> fixed-point (2^38) integer atomic
// (deterministic: integer adds commute exactly) -> last block finalizes and
// resets state for the next graph replay.

#define NPTS  1024
#define SEGN  256
#define FXP   274877906944.0   // 2^38

__device__ unsigned long long g_acc;    // zero-initialized; reset each launch
__device__ unsigned int       g_count;  // zero-initialized; reset each launch

__global__ __launch_bounds__(256, 8)
void xing_fused_kernel(const float* __restrict__ x,
                       const void* __restrict__ scale_ptr,
                       float* __restrict__ out, int P)
{
    __shared__ float red[8];

    const int p = blockIdx.x;
    const int t = threadIdx.x;

    // Thread t = segment t of row p. Needs points 3t..3t+3 -> floats [6t, 6t+8).
    // 8B-aligned float2 loads; warp spans 776 B (24-25 sectors), adjacent warps
    // overlap by 8 B only -> DRAM traffic ~= unique bytes.
    const float* __restrict__ base = x + (size_t)p * (NPTS * 2) + t * 6;
    const float2 p0 = *reinterpret_cast<const float2*>(base + 0);
    const float2 p1 = *reinterpret_cast<const float2*>(base + 2);
    const float2 p2 = *reinterpret_cast<const float2*>(base + 4);
    const float2 p3 = *reinterpret_cast<const float2*>(base + 6);

    const float v1x = p1.x - p0.x, v1y = p1.y - p0.y;
    const float v2x = p2.x - p1.x, v2y = p2.y - p1.y;
    const float v3x = p3.x - p2.x, v3y = p3.y - p2.y;

    // sign(s12) == sign(cross12): norms are positive a.s.
    const float c12 = v1x * v2y - v1y * v2x;
    const float c13 = v1x * v3y - v1y * v3x;
    const float nn  = (v1x * v1x + v1y * v1y) * (v3x * v3x + v3y * v3y);
    const float sina = c13 * rsqrtf(nn);

    float term = (c12 >= 0.0f) ? fmaxf(-sina, 0.0f) : fmaxf(sina, 0.0f);

    // Warp reduce (8 warps)
    #pragma unroll
    for (int off = 16; off > 0; off >>= 1)
        term += __shfl_xor_sync(0xFFFFFFFFu, term, off);
    if ((t & 31) == 0) red[t >> 5] = term;
    __syncthreads();

    if (t == 0) {
        float rowsum = red[0];
        #pragma unroll
        for (int w = 1; w < 8; w++) rowsum += red[w];

        // Deterministic fixed-point accumulation (term >= 0, rowsum in [0,256];
        // P*256*2^38 ~ 1.2e18 < 2^63).
        const long long q = __double2ll_rn((double)rowsum * FXP);
        atomicAdd(&g_acc, (unsigned long long)q);

        __threadfence();
        const unsigned int done = atomicAdd(&g_count, 1u);
        if (done == (unsigned int)(gridDim.x - 1)) {
            // All blocks' g_acc contributions are visible (fence->counter order).
            const unsigned long long bits = atomicAdd(&g_acc, 0ULL);
            const double total = (double)(long long)bits / FXP;

            // scale may be int32 or float32 (1 element): bit-pattern heuristic.
            const int   ibits = *reinterpret_cast<const int*>(scale_ptr);
            const float fval  = __int_as_float(ibits);
            const float af    = fabsf(fval);
            const double scale = (af >= 1e-30f && af <= 1e30f) ? (double)fval
                                                               : (double)ibits;

            out[0] = (float)(total * scale / ((double)SEGN * (double)P));

            // Reset for the next graph replay (stream-ordered, no race:
            // every block has already passed its g_acc add + counter add).
            atomicExch(&g_acc, 0ULL);
            atomicExch(&g_count, 0u);
        }
    }
}

extern "C" void kernel_launch(void* const* d_in, const int* in_sizes, int n_in,
                              void* d_out, int out_size)
{
    const float* x = (const float*)d_in[0];
    const void* scale = (n_in > 1) ? d_in[1] : nullptr;

    const int P = in_sizes[0] / (NPTS * 2);   // 16384 for this problem

    xing_fused_kernel<<<P, 256>>>(x, scale, (float*)d_out, P);
}